// round 12
// baseline (speedup 1.0000x reference)
#include <cuda_runtime.h>

#define LOG2E 1.4426950408889634f
#define N_EN  20000
#define M_MEN 256
#define TN 64   // entities per block (threadIdx.x)
#define MG 4    // mention-groups per block (threadIdx.y)
#define RM 8    // mentions per thread

__device__ __forceinline__ float ex2f(float x){float r;asm("ex2.approx.ftz.f32 %0,%1;":"=f"(r):"f"(x));return r;}
__device__ __forceinline__ float lg2f(float x){float r;asm("lg2.approx.ftz.f32 %0,%1;":"=f"(r):"f"(x));return r;}

// Deg-6 poly Q(t) ~= log2(1+t) on [0,1] (closed-form Chebyshev, z=3-2*sqrt2).
// Q(0)=3.84e-6 > 0 keeps chunk products positive. Scalar Horner with literal
// coefficients: no packed registers, no pk/upk MOVs, 1 independent chain per
// element (4 chains in flight per chunk).
__device__ __forceinline__ float q_log2_1p(float t){
    float q = fmaf(-0.02512518f, t, 0.1193046f);
    q = fmaf(q, t, -0.2746312f);
    q = fmaf(q, t,  0.4555314f);
    q = fmaf(q, t, -0.7175598f);
    q = fmaf(q, t,  1.4424753f);
    q = fmaf(q, t,  3.84e-6f);
    return q;
}

// One 8-dim chunk: returns lg2( prod_d v_d ), v_d = log2(1 + 2^{y_d}),
// y = min(mZ,eZ) - max(mz,ez) (inputs prescaled by log2e).
// dims 0-3: MUFU path  v = lg2(1+ex2(y))
// dims 4-7: poly path  v = relu(y) + t*Q'(t), t = 2^-|y|   (scalar fma pipe)
__device__ __forceinline__ float chunk_lg2(const float* mz, const float* mZ,
                                           const float* ez, const float* eZ){
    float va[4];
#pragma unroll
    for (int d = 0; d < 4; ++d){
        float y = fminf(mZ[d], eZ[d]) - fmaxf(mz[d], ez[d]);
        va[d] = lg2f(1.f + ex2f(y));
    }
    float vb[4];
#pragma unroll
    for (int d = 0; d < 4; ++d){
        float y = fminf(mZ[4+d], eZ[4+d]) - fmaxf(mz[4+d], ez[4+d]);
        float t = ex2f(-fabsf(y));
        vb[d] = fmaxf(y, 0.f) + q_log2_1p(t);   // v = relu(y) + Q(t) > 0
    }
    float t1 = va[0] * va[1];
    float t2 = va[2] * va[3];
    float t3 = vb[0] * vb[1];
    float t4 = vb[2] * vb[3];
    return lg2f((t1 * t2) * (t3 * t4));
}

__device__ __forceinline__ void load8(const float* p, float* v){
    float4 a = *(const float4*)p;
    float4 b = *(const float4*)(p + 4);
    v[0]=a.x; v[1]=a.y; v[2]=a.z; v[3]=a.w;
    v[4]=b.x; v[5]=b.y; v[6]=b.z; v[7]=b.w;
}
__device__ __forceinline__ void load8s(const float* p, float* v){
    float4 a = *(const float4*)p;
    float4 b = *(const float4*)(p + 4);
    v[0]=a.x*LOG2E; v[1]=a.y*LOG2E; v[2]=a.z*LOG2E; v[3]=a.w*LOG2E;
    v[4]=b.x*LOG2E; v[5]=b.y*LOG2E; v[6]=b.z*LOG2E; v[7]=b.w*LOG2E;
}

__global__ __launch_bounds__(256, 3) void ivr_kernel(const float* __restrict__ men,
                                                     const float* __restrict__ en,
                                                     float* __restrict__ out){
    __shared__ float s_men[32][128];   // 32 mentions, prescaled by log2e
    __shared__ float s_gmp[256];
    __shared__ float s_gm[32];

    const int tid = threadIdx.y * TN + threadIdx.x;
    const int m0  = blockIdx.y * 32;

#pragma unroll
    for (int i = 0; i < 16; ++i){
        int idx = tid + i * 256;
        s_men[idx >> 7][idx & 127] = men[m0 * 128 + idx] * LOG2E;
    }
    __syncthreads();

    // per-mention self volume (identical value path -> approx error cancels)
    {
        int mi = tid >> 3, ci = tid & 7;
        float mzv[8], mZv[8];
        load8(&s_men[mi][ci*8],      mzv);
        load8(&s_men[mi][64 + ci*8], mZv);
        s_gmp[tid] = chunk_lg2(mzv, mZv, mzv, mZv);
    }
    __syncthreads();
    if (tid < 32){
        float s = 0.f;
#pragma unroll
        for (int i = 0; i < 8; ++i) s += s_gmp[tid*8 + i];
        s_gm[tid] = s;
    }
    __syncthreads();

    const int n = blockIdx.x * TN + threadIdx.x;
    if (n >= N_EN) return;

    const int mg = threadIdx.y;
    float acc[RM];
#pragma unroll
    for (int j = 0; j < RM; ++j) acc[j] = 0.f;

    const float* erow = en + (size_t)n * 128;

#pragma unroll 1
    for (int c = 0; c < 8; ++c){
        float ez[8], eZ[8];
        load8s(erow + c*8,      ez);
        load8s(erow + 64 + c*8, eZ);

#pragma unroll
        for (int j = 0; j < RM; ++j){
            float mzv[8], mZv[8];
            load8(&s_men[mg*RM + j][c*8],      mzv);   // smem broadcast
            load8(&s_men[mg*RM + j][64 + c*8], mZv);
            acc[j] += chunk_lg2(mzv, mZv, ez, eZ);
        }
    }

#pragma unroll
    for (int j = 0; j < RM; ++j){
        int m = m0 + mg*RM + j;
        out[(size_t)m * N_EN + n] = ex2f(acc[j] - s_gm[mg*RM + j]);
    }
}

extern "C" void kernel_launch(void* const* d_in, const int* in_sizes, int n_in,
                              void* d_out, int out_size){
    const float* men = (const float*)d_in[0];
    const float* en  = (const float*)d_in[1];
    if (n_in >= 2 && in_sizes[0] > in_sizes[1]){
        const float* t = men; men = en; en = t;
    }
    float* out = (float*)d_out;

    dim3 block(TN, MG);
    dim3 grid((N_EN + TN - 1) / TN, M_MEN / (MG * RM));
    ivr_kernel<<<grid, block>>>(men, en, out);
}

// round 13
// speedup vs baseline: 1.0023x; 1.0023x over previous
#include <cuda_runtime.h>

#define LOG2E 1.4426950408889634f
#define N_EN  20000
#define M_MEN 256

// Block: 256 threads = 8 warps. Warp = 4 entities x 8 chunk-slots.
//   lane = n_sub*8 + c  (n_sub in 0..3, c in 0..7)
// Each thread: entity chunk (n, c) in REGISTERS, loops 32 mentions,
// loads mention chunk (m, c) from padded smem (8 distinct addrs/warp,
// conflict-free), computes one 8-dim chunk, shfl-reduces over c.
// Entities/block = 32 (20000 = 625*32), mention tiles = 8 x 32.

__device__ __forceinline__ float ex2f(float x){float r;asm("ex2.approx.ftz.f32 %0,%1;":"=f"(r):"f"(x));return r;}
__device__ __forceinline__ float lg2f(float x){float r;asm("lg2.approx.ftz.f32 %0,%1;":"=f"(r):"f"(x));return r;}

// Deg-6 poly Q(t) ~= log2(1+t) on [0,1] (closed-form Chebyshev, z=3-2*sqrt2).
// Q(0)=3.84e-6 > 0 keeps chunk products positive.
__device__ __forceinline__ float q_log2_1p(float t){
    float q = fmaf(-0.02512518f, t, 0.1193046f);
    q = fmaf(q, t, -0.2746312f);
    q = fmaf(q, t,  0.4555314f);
    q = fmaf(q, t, -0.7175598f);
    q = fmaf(q, t,  1.4424753f);
    q = fmaf(q, t,  3.84e-6f);
    return q;
}

// One 8-dim chunk: lg2( prod_d log2(1+2^{y_d}) ), y = min(mZ,eZ)-max(mz,ez).
// ml: 16 floats (lo[0..7], hi[8..15]) for the mention chunk; ez/eZ: entity regs.
// dims 0-3: MUFU path; dims 4-7: scalar-poly path (fma pipe).
__device__ __forceinline__ float chunk_lg2(const float* ml,
                                           const float* ez, const float* eZ){
    float va[4];
#pragma unroll
    for (int d = 0; d < 4; ++d){
        float y = fminf(ml[8+d], eZ[d]) - fmaxf(ml[d], ez[d]);
        va[d] = lg2f(1.f + ex2f(y));
    }
    float vb[4];
#pragma unroll
    for (int d = 0; d < 4; ++d){
        float y = fminf(ml[12+d], eZ[4+d]) - fmaxf(ml[4+d], ez[4+d]);
        float t = ex2f(-fabsf(y));
        vb[d] = fmaxf(y, 0.f) + q_log2_1p(t);
    }
    float t1 = va[0] * va[1];
    float t2 = va[2] * va[3];
    float t3 = vb[0] * vb[1];
    float t4 = vb[2] * vb[3];
    return lg2f((t1 * t2) * (t3 * t4));
}

// Padded mention smem: per mention 8 chunks x 20 floats (16 data + 4 pad).
// Chunk base stride 80B -> the 8 c-addresses hit disjoint bank groups.
#define MSTR 160   // floats per mention row (8*20)

__global__ __launch_bounds__(256, 3) void ivr_kernel(const float* __restrict__ men,
                                                     const float* __restrict__ en,
                                                     float* __restrict__ out){
    __shared__ float s_men[32 * MSTR];   // 32 mentions, padded, prescaled by log2e
    __shared__ float s_gmp[256];
    __shared__ float s_gm[32];

    const int tid  = threadIdx.x;
    const int lane = tid & 31;
    const int wid  = tid >> 5;
    const int c    = lane & 7;        // chunk slot
    const int nsub = lane >> 3;       // entity within warp
    const int m0   = blockIdx.y * 32;

    // stage + prescale + pad-pack mention tile
    for (int idx = tid; idx < 32 * 128; idx += 256){
        int m = idx >> 7, d = idx & 127;
        int cc = (d & 63) >> 3, k = d & 7, off = (d >= 64) ? 8 : 0;
        s_men[m * MSTR + cc * 20 + off + k] = men[(m0 + m) * 128 + d] * LOG2E;
    }
    __syncthreads();

    // per-mention self volume: thread (mi, ci), same chunk value path
    {
        int mi = tid >> 3, ci = tid & 7;
        const float* p = s_men + mi * MSTR + ci * 20;
        float ml[16];
#pragma unroll
        for (int k = 0; k < 16; ++k) ml[k] = p[k];
        s_gmp[tid] = chunk_lg2(ml, ml, ml + 8);   // ez = lo, eZ = hi (self)
    }
    __syncthreads();
    if (tid < 32){
        float s = 0.f;
#pragma unroll
        for (int i = 0; i < 8; ++i) s += s_gmp[tid * 8 + i];
        s_gm[tid] = s;
    }
    __syncthreads();

    // entity chunk -> registers (prescaled). 20000 = 625*32, no guard.
    const int n = blockIdx.x * 32 + wid * 4 + nsub;
    float ez[8], eZ[8];
    {
        const float* erow = en + (size_t)n * 128;
        float4 a0 = *(const float4*)(erow + c * 8);
        float4 a1 = *(const float4*)(erow + c * 8 + 4);
        float4 b0 = *(const float4*)(erow + 64 + c * 8);
        float4 b1 = *(const float4*)(erow + 64 + c * 8 + 4);
        ez[0]=a0.x*LOG2E; ez[1]=a0.y*LOG2E; ez[2]=a0.z*LOG2E; ez[3]=a0.w*LOG2E;
        ez[4]=a1.x*LOG2E; ez[5]=a1.y*LOG2E; ez[6]=a1.z*LOG2E; ez[7]=a1.w*LOG2E;
        eZ[0]=b0.x*LOG2E; eZ[1]=b0.y*LOG2E; eZ[2]=b0.z*LOG2E; eZ[3]=b0.w*LOG2E;
        eZ[4]=b1.x*LOG2E; eZ[5]=b1.y*LOG2E; eZ[6]=b1.z*LOG2E; eZ[7]=b1.w*LOG2E;
    }

    const float* mbase = s_men + c * 20;

#pragma unroll 2
    for (int m = 0; m < 32; ++m){
        const float* p = mbase + m * MSTR;
        float ml[16];
        {   // 4x LDS.128: 8 distinct 16B addrs/warp, disjoint bank groups
            float4 q0 = *(const float4*)(p);
            float4 q1 = *(const float4*)(p + 4);
            float4 q2 = *(const float4*)(p + 8);
            float4 q3 = *(const float4*)(p + 12);
            ml[0]=q0.x; ml[1]=q0.y; ml[2]=q0.z;  ml[3]=q0.w;
            ml[4]=q1.x; ml[5]=q1.y; ml[6]=q1.z;  ml[7]=q1.w;
            ml[8]=q2.x; ml[9]=q2.y; ml[10]=q2.z; ml[11]=q2.w;
            ml[12]=q3.x; ml[13]=q3.y; ml[14]=q3.z; ml[15]=q3.w;
        }
        float v = chunk_lg2(ml, ez, eZ);
        // reduce over the 8 chunk lanes (masks touch only c bits)
        v += __shfl_xor_sync(0xFFFFFFFFu, v, 1);
        v += __shfl_xor_sync(0xFFFFFFFFu, v, 2);
        v += __shfl_xor_sync(0xFFFFFFFFu, v, 4);
        if (c == 0){
            out[(size_t)(m0 + m) * N_EN + n] = ex2f(v - s_gm[m]);
        }
    }
}

extern "C" void kernel_launch(void* const* d_in, const int* in_sizes, int n_in,
                              void* d_out, int out_size){
    const float* men = (const float*)d_in[0];
    const float* en  = (const float*)d_in[1];
    if (n_in >= 2 && in_sizes[0] > in_sizes[1]){
        const float* t = men; men = en; en = t;
    }
    float* out = (float*)d_out;

    dim3 grid(N_EN / 32, M_MEN / 32);   // 625 x 8
    ivr_kernel<<<grid, 256>>>(men, en, out);
}

// round 14
// speedup vs baseline: 1.1141x; 1.1116x over previous
#include <cuda_runtime.h>

#define LOG2E 1.4426950408889634f
#define N_EN  20000
#define M_MEN 256

// Block: 256 threads = 8 warps. Warp = 4 entities x 8 chunk-slots.
//   lane = n_sub*8 + c  (n_sub in 0..3, c in 0..7)
// Thread: entity chunk (n, c) in registers; loops 32 mentions; mention chunk
// from padded smem (8 distinct addrs/warp, conflict-free); shfl-reduce over c.
// Split per 8-dim chunk: 5 dims MUFU path, 3 dims scalar-poly path
// (slot/MUFU balance point of the measured model: slots=145-6a, mufu=8(a+9)).

__device__ __forceinline__ float ex2f(float x){float r;asm("ex2.approx.ftz.f32 %0,%1;":"=f"(r):"f"(x));return r;}
__device__ __forceinline__ float lg2f(float x){float r;asm("lg2.approx.ftz.f32 %0,%1;":"=f"(r):"f"(x));return r;}

// Deg-6 poly Q(t) ~= log2(1+t) on [0,1] (closed-form Chebyshev, z=3-2*sqrt2).
// Q(0)=3.84e-6 > 0 keeps chunk products positive.
__device__ __forceinline__ float q_log2_1p(float t){
    float q = fmaf(-0.02512518f, t, 0.1193046f);
    q = fmaf(q, t, -0.2746312f);
    q = fmaf(q, t,  0.4555314f);
    q = fmaf(q, t, -0.7175598f);
    q = fmaf(q, t,  1.4424753f);
    q = fmaf(q, t,  3.84e-6f);
    return q;
}

// One 8-dim chunk: lg2( prod_d log2(1+2^{y_d}) ), y = min(mZ,eZ)-max(mz,ez).
// ml: 16 floats (lo[0..7], hi[8..15]); ez/eZ: entity registers.
__device__ __forceinline__ float chunk_lg2(const float* ml,
                                           const float* ez, const float* eZ){
    float va[5];
#pragma unroll
    for (int d = 0; d < 5; ++d){
        float y = fminf(ml[8+d], eZ[d]) - fmaxf(ml[d], ez[d]);
        va[d] = lg2f(1.f + ex2f(y));
    }
    float vb[3];
#pragma unroll
    for (int d = 5; d < 8; ++d){
        float y = fminf(ml[8+d], eZ[d]) - fmaxf(ml[d], ez[d]);
        float t = ex2f(-fabsf(y));
        vb[d-5] = fmaxf(y, 0.f) + q_log2_1p(t);
    }
    float t1 = va[0] * va[1];
    float t2 = va[2] * va[3];
    float t3 = va[4] * vb[0];
    float t4 = vb[1] * vb[2];
    return lg2f((t1 * t2) * (t3 * t4));
}

// Padded mention smem: per mention 8 chunks x 20 floats (16 data + 4 pad);
// chunk stride 80B -> 8 c-addresses in disjoint bank groups.
#define MSTR 160

__global__ __launch_bounds__(256, 4) void ivr_kernel(const float* __restrict__ men,
                                                     const float* __restrict__ en,
                                                     float* __restrict__ out){
    __shared__ float s_men[32 * MSTR];
    __shared__ float s_gmp[256];
    __shared__ float s_gm[32];

    const int tid  = threadIdx.x;
    const int lane = tid & 31;
    const int wid  = tid >> 5;
    const int c    = lane & 7;
    const int nsub = lane >> 3;
    const int m0   = blockIdx.y * 32;

    for (int idx = tid; idx < 32 * 128; idx += 256){
        int m = idx >> 7, d = idx & 127;
        int cc = (d & 63) >> 3, k = d & 7, off = (d >= 64) ? 8 : 0;
        s_men[m * MSTR + cc * 20 + off + k] = men[(m0 + m) * 128 + d] * LOG2E;
    }
    __syncthreads();

    // per-mention self volume (identical value path -> approx error cancels)
    {
        int mi = tid >> 3, ci = tid & 7;
        const float* p = s_men + mi * MSTR + ci * 20;
        float ml[16];
#pragma unroll
        for (int k = 0; k < 16; ++k) ml[k] = p[k];
        s_gmp[tid] = chunk_lg2(ml, ml, ml + 8);
    }
    __syncthreads();
    if (tid < 32){
        float s = 0.f;
#pragma unroll
        for (int i = 0; i < 8; ++i) s += s_gmp[tid * 8 + i];
        s_gm[tid] = s;
    }
    __syncthreads();

    // entity chunk -> registers (prescaled). 20000 = 625*32, no guard.
    const int n = blockIdx.x * 32 + wid * 4 + nsub;
    float ez[8], eZ[8];
    {
        const float* erow = en + (size_t)n * 128;
        float4 a0 = *(const float4*)(erow + c * 8);
        float4 a1 = *(const float4*)(erow + c * 8 + 4);
        float4 b0 = *(const float4*)(erow + 64 + c * 8);
        float4 b1 = *(const float4*)(erow + 64 + c * 8 + 4);
        ez[0]=a0.x*LOG2E; ez[1]=a0.y*LOG2E; ez[2]=a0.z*LOG2E; ez[3]=a0.w*LOG2E;
        ez[4]=a1.x*LOG2E; ez[5]=a1.y*LOG2E; ez[6]=a1.z*LOG2E; ez[7]=a1.w*LOG2E;
        eZ[0]=b0.x*LOG2E; eZ[1]=b0.y*LOG2E; eZ[2]=b0.z*LOG2E; eZ[3]=b0.w*LOG2E;
        eZ[4]=b1.x*LOG2E; eZ[5]=b1.y*LOG2E; eZ[6]=b1.z*LOG2E; eZ[7]=b1.w*LOG2E;
    }

    const float* mbase = s_men + c * 20;

#pragma unroll 8
    for (int m = 0; m < 32; ++m){
        const float* p = mbase + m * MSTR;
        float ml[16];
        {
            float4 q0 = *(const float4*)(p);
            float4 q1 = *(const float4*)(p + 4);
            float4 q2 = *(const float4*)(p + 8);
            float4 q3 = *(const float4*)(p + 12);
            ml[0]=q0.x;  ml[1]=q0.y;  ml[2]=q0.z;  ml[3]=q0.w;
            ml[4]=q1.x;  ml[5]=q1.y;  ml[6]=q1.z;  ml[7]=q1.w;
            ml[8]=q2.x;  ml[9]=q2.y;  ml[10]=q2.z; ml[11]=q2.w;
            ml[12]=q3.x; ml[13]=q3.y; ml[14]=q3.z; ml[15]=q3.w;
        }
        float v = chunk_lg2(ml, ez, eZ);
        v += __shfl_xor_sync(0xFFFFFFFFu, v, 1);
        v += __shfl_xor_sync(0xFFFFFFFFu, v, 2);
        v += __shfl_xor_sync(0xFFFFFFFFu, v, 4);
        if (c == 0){
            out[(size_t)(m0 + m) * N_EN + n] = ex2f(v - s_gm[m]);
        }
    }
}

extern "C" void kernel_launch(void* const* d_in, const int* in_sizes, int n_in,
                              void* d_out, int out_size){
    const float* men = (const float*)d_in[0];
    const float* en  = (const float*)d_in[1];
    if (n_in >= 2 && in_sizes[0] > in_sizes[1]){
        const float* t = men; men = en; en = t;
    }
    float* out = (float*)d_out;

    dim3 grid(N_EN / 32, M_MEN / 32);   // 625 x 8
    ivr_kernel<<<grid, 256>>>(men, en, out);
}